// round 1
// baseline (speedup 1.0000x reference)
#include <cuda_runtime.h>
#include <cuda_bf16.h>
#include <math.h>

// Problem dims
#define B    16
#define C    256
#define O    256
#define HW   56
#define NK   8     // number of kernel banks
#define HID  64

// Conv tiling
#define ICB   8    // input-channel chunk
#define ROWS  16   // spatial rows per block
#define OT    8    // output channels per block
#define TPB   224  // 56 x 4 threads

__device__ float g_pooled[B * C];
__device__ float g_alphas[B * NK];

// ---------------- Kernel A: global average pool ----------------
__global__ void pool_kernel(const float* __restrict__ x) {
    int c = blockIdx.x;
    int b = blockIdx.y;
    const float* p = x + ((long)(b * C + c)) * (HW * HW);
    float s = 0.f;
    for (int i = threadIdx.x; i < HW * HW; i += 256) s += p[i];
    __shared__ float red[8];
    #pragma unroll
    for (int o = 16; o > 0; o >>= 1) s += __shfl_xor_sync(0xffffffffu, s, o);
    if ((threadIdx.x & 31) == 0) red[threadIdx.x >> 5] = s;
    __syncthreads();
    if (threadIdx.x < 8) {
        s = red[threadIdx.x];
        #pragma unroll
        for (int o = 4; o > 0; o >>= 1) s += __shfl_xor_sync(0xffu, s, o);
        if (threadIdx.x == 0)
            g_pooled[b * C + c] = s * (1.0f / (HW * HW));
    }
}

// ---------------- Kernel B: MLP + softmax -> alphas ----------------
__global__ void mlp_kernel(const float* __restrict__ w1, const float* __restrict__ b1,
                           const float* __restrict__ w2, const float* __restrict__ b2) {
    __shared__ float sp[B * C];
    __shared__ float sh[B * HID];
    __shared__ float sc[B * NK];
    int tid = threadIdx.x;
    for (int i = tid; i < B * C; i += 256) sp[i] = g_pooled[i];
    __syncthreads();
    for (int t = tid; t < B * HID; t += 256) {
        int b = t >> 6, j = t & 63;
        float s = b1[j];
        #pragma unroll 8
        for (int c = 0; c < C; c++) s = fmaf(sp[b * C + c], w1[c * HID + j], s);
        sh[t] = fmaxf(s, 0.f);
    }
    __syncthreads();
    if (tid < B * NK) {
        int b = tid >> 3, k = tid & 7;
        float s = b2[k];
        #pragma unroll
        for (int j = 0; j < HID; j++) s = fmaf(sh[b * HID + j], w2[j * NK + k], s);
        sc[tid] = s;
    }
    __syncthreads();
    if (tid < B) {
        float m = -1e30f;
        #pragma unroll
        for (int k = 0; k < NK; k++) m = fmaxf(m, sc[tid * NK + k]);
        float e[NK], sum = 0.f;
        #pragma unroll
        for (int k = 0; k < NK; k++) { e[k] = __expf(sc[tid * NK + k] - m); sum += e[k]; }
        float inv = 1.0f / sum;
        #pragma unroll
        for (int k = 0; k < NK; k++) g_alphas[tid * NK + k] = e[k] * inv;
    }
}

// ---------------- Kernel C: fused mix + 3x3 conv ----------------
// Block: (b, 8 output channels, 16-row x 56-col spatial tile)
// Thread (tx, ty): columns tx, rows {ty + 4j, j=0..3}, 8 output channels -> 32 accumulators.
__global__ __launch_bounds__(TPB)
void conv_kernel(const float* __restrict__ x, const float* __restrict__ kern,
                 float* __restrict__ out) {
    __shared__ float sx[ICB][ROWS + 2][HW + 2];   // 8 x 18 x 58
    __shared__ float sw[OT][ICB][9];
    __shared__ float sal[NK];

    const int tx = threadIdx.x;            // 0..55
    const int ty = threadIdx.y;            // 0..3
    const int tid = ty * HW + tx;          // 0..223
    const int row0 = blockIdx.x * ROWS;    // 0,16,32,48 (last tile partial)
    const int o0 = blockIdx.y * OT;
    const int b = blockIdx.z;

    if (tid < NK) sal[tid] = g_alphas[b * NK + tid];

    float acc[4][OT];
    #pragma unroll
    for (int j = 0; j < 4; j++)
        #pragma unroll
        for (int o = 0; o < OT; o++) acc[j][o] = 0.f;

    const float* xb = x + (long)b * C * HW * HW;

    for (int ic0 = 0; ic0 < C; ic0 += ICB) {
        // ---- load x tile (with halo, zero-filled OOB) ----
        #pragma unroll 4
        for (int idx = tid; idx < ICB * (ROWS + 2) * (HW + 2); idx += TPB) {
            int ic = idx / ((ROWS + 2) * (HW + 2));
            int r  = (idx / (HW + 2)) % (ROWS + 2);
            int cc = idx % (HW + 2);
            int gh = row0 - 1 + r;
            int gw = cc - 1;
            float v = 0.f;
            if (gh >= 0 && gh < HW && gw >= 0 && gw < HW)
                v = xb[((ic0 + ic) * HW + gh) * HW + gw];
            sx[ic][r][cc] = v;
        }
        // ---- mix weights: sw[o][ic][p] = sum_k alpha[k] * kern[k][o0+o][ic0+ic][p] ----
        for (int e = tid; e < OT * ICB * 9; e += TPB) {
            int p = e % 9;
            int t = e / 9;
            int ic = t % ICB;
            int o  = t / ICB;
            int base = (((o0 + o) * C) + (ic0 + ic)) * 9 + p;
            float s = 0.f;
            #pragma unroll
            for (int k = 0; k < NK; k++)
                s = fmaf(sal[k], kern[k * (O * C * 9) + base], s);
            sw[o][ic][p] = s;
        }
        __syncthreads();

        // ---- compute ----
        #pragma unroll
        for (int ic = 0; ic < ICB; ic++) {
            #pragma unroll
            for (int kh = 0; kh < 3; kh++) {
                #pragma unroll
                for (int kw = 0; kw < 3; kw++) {
                    float wv[OT];
                    #pragma unroll
                    for (int o = 0; o < OT; o++) wv[o] = sw[o][ic][kh * 3 + kw];
                    #pragma unroll
                    for (int j = 0; j < 4; j++) {
                        float xv = sx[ic][ty + 4 * j + kh][tx + kw];
                        #pragma unroll
                        for (int o = 0; o < OT; o++)
                            acc[j][o] = fmaf(wv[o], xv, acc[j][o]);
                    }
                }
            }
        }
        __syncthreads();
    }

    // ---- store ----
    #pragma unroll
    for (int j = 0; j < 4; j++) {
        int row = row0 + ty + 4 * j;
        if (row < HW) {
            #pragma unroll
            for (int o = 0; o < OT; o++)
                out[(((long)b * O + (o0 + o)) * HW + row) * HW + tx] = acc[j][o];
        }
    }
}

extern "C" void kernel_launch(void* const* d_in, const int* in_sizes, int n_in,
                              void* d_out, int out_size) {
    const float* x    = (const float*)d_in[0];
    const float* kern = (const float*)d_in[1];
    const float* w1   = (const float*)d_in[2];
    const float* b1   = (const float*)d_in[3];
    const float* w2   = (const float*)d_in[4];
    const float* b2   = (const float*)d_in[5];
    float* out = (float*)d_out;

    pool_kernel<<<dim3(C, B), 256>>>(x);
    mlp_kernel<<<1, 256>>>(w1, b1, w2, b2);
    dim3 grid((HW + ROWS - 1) / ROWS, O / OT, B);   // 4 x 32 x 16
    dim3 block(HW, 4);                               // 224 threads
    conv_kernel<<<grid, block>>>(x, kern, out);
}

// round 2
// speedup vs baseline: 1.2014x; 1.2014x over previous
#include <cuda_runtime.h>
#include <cuda_bf16.h>
#include <math.h>

// Problem dims
#define B    16
#define C    256
#define O    256
#define HW   56
#define NK   8
#define HID  64

// Conv tiling
#define ICB   8     // input-channel chunk
#define ROWS  16    // spatial rows per block
#define OT    8     // output channels per block (4 f32x2 pairs)
#define TPB   224   // 56 x 4 threads

typedef unsigned long long ull;

__device__ __forceinline__ ull ffma2(ull a, ull b, ull c) {
    ull d;
    asm("fma.rn.f32x2 %0, %1, %2, %3;" : "=l"(d) : "l"(a), "l"(b), "l"(c));
    return d;
}
__device__ __forceinline__ ull pack2(float lo, float hi) {
    ull d;
    asm("mov.b64 %0, {%1, %2};" : "=l"(d) : "f"(lo), "f"(hi));
    return d;
}
__device__ __forceinline__ void unpack2(ull v, float& lo, float& hi) {
    asm("mov.b64 {%0, %1}, %2;" : "=f"(lo), "=f"(hi) : "l"(v));
}

__device__ float g_pooled[B * C];
__device__ float g_alphas[B * NK];

// ---------------- Kernel A: global average pool (vectorized) ----------------
__global__ void pool_kernel(const float* __restrict__ x) {
    int c = blockIdx.x;
    int b = blockIdx.y;
    const float4* p = (const float4*)(x + ((long)(b * C + c)) * (HW * HW));
    float s = 0.f;
    #pragma unroll
    for (int i = threadIdx.x; i < (HW * HW) / 4; i += 256) {
        float4 v = p[i];
        s += (v.x + v.y) + (v.z + v.w);
    }
    __shared__ float red[8];
    #pragma unroll
    for (int o = 16; o > 0; o >>= 1) s += __shfl_xor_sync(0xffffffffu, s, o);
    if ((threadIdx.x & 31) == 0) red[threadIdx.x >> 5] = s;
    __syncthreads();
    if (threadIdx.x < 8) {
        s = red[threadIdx.x];
        #pragma unroll
        for (int o = 4; o > 0; o >>= 1) s += __shfl_xor_sync(0xffu, s, o);
        if (threadIdx.x == 0)
            g_pooled[b * C + c] = s * (1.0f / (HW * HW));
    }
}

// ---------------- Kernel B: MLP + softmax -> alphas ----------------
__global__ void mlp_kernel(const float* __restrict__ w1, const float* __restrict__ b1,
                           const float* __restrict__ w2, const float* __restrict__ b2) {
    __shared__ float sp[B * C];
    __shared__ float sh[B * HID];
    __shared__ float sc[B * NK];
    int tid = threadIdx.x;
    for (int i = tid; i < B * C; i += 256) sp[i] = g_pooled[i];
    __syncthreads();
    for (int t = tid; t < B * HID; t += 256) {
        int b = t >> 6, j = t & 63;
        float s = b1[j];
        #pragma unroll 8
        for (int c = 0; c < C; c++) s = fmaf(sp[b * C + c], w1[c * HID + j], s);
        sh[t] = fmaxf(s, 0.f);
    }
    __syncthreads();
    if (tid < B * NK) {
        int b = tid >> 3, k = tid & 7;
        float s = b2[k];
        #pragma unroll
        for (int j = 0; j < HID; j++) s = fmaf(sh[b * HID + j], w2[j * NK + k], s);
        sc[tid] = s;
    }
    __syncthreads();
    if (tid < B) {
        float m = -1e30f;
        #pragma unroll
        for (int k = 0; k < NK; k++) m = fmaxf(m, sc[tid * NK + k]);
        float e[NK], sum = 0.f;
        #pragma unroll
        for (int k = 0; k < NK; k++) { e[k] = __expf(sc[tid * NK + k] - m); sum += e[k]; }
        float inv = 1.0f / sum;
        #pragma unroll
        for (int k = 0; k < NK; k++) g_alphas[tid * NK + k] = e[k] * inv;
    }
}

// ---------------- Kernel C: fused mix + 3x3 conv with f32x2 FMA ----------------
// Block: (b, 8 output channels, 16-row x 56-col spatial tile)
// Thread (tx, ty): column tx, rows {ty + 4j, j=0..3}, 8 output chans as 4 f32x2 pairs.
__global__ __launch_bounds__(TPB, 3)
void conv_kernel(const float* __restrict__ x, const float* __restrict__ kern,
                 float* __restrict__ out) {
    __shared__ float sx[ICB][ROWS + 2][HW + 2];          // 8 x 18 x 58
    __shared__ __align__(16) float sw[ICB][9][OT];       // o innermost, 32B rows
    __shared__ float sal[NK];

    const int tx = threadIdx.x;            // 0..55
    const int ty = threadIdx.y;            // 0..3
    const int tid = ty * HW + tx;          // 0..223
    const int row0 = blockIdx.x * ROWS;
    const int o0 = blockIdx.y * OT;
    const int b = blockIdx.z;

    if (tid < NK) sal[tid] = g_alphas[b * NK + tid];

    ull acc[4][4];                         // [j][o-pair]
    #pragma unroll
    for (int j = 0; j < 4; j++)
        #pragma unroll
        for (int q = 0; q < 4; q++) acc[j][q] = 0ull;

    const float* xb = x + (long)b * C * HW * HW;

    for (int ic0 = 0; ic0 < C; ic0 += ICB) {
        // ---- load x tile (with halo, zero-filled OOB) ----
        #pragma unroll 4
        for (int idx = tid; idx < ICB * (ROWS + 2) * (HW + 2); idx += TPB) {
            int ic = idx / ((ROWS + 2) * (HW + 2));
            int r  = (idx / (HW + 2)) % (ROWS + 2);
            int cc = idx % (HW + 2);
            int gh = row0 - 1 + r;
            int gw = cc - 1;
            float v = 0.f;
            if (gh >= 0 && gh < HW && gw >= 0 && gw < HW)
                v = xb[((ic0 + ic) * HW + gh) * HW + gw];
            sx[ic][r][cc] = v;
        }
        // ---- mix weights: sw[ic][p][o] = sum_k alpha[k]*kern[k][o0+o][ic0+ic][p] ----
        // p innermost across threads => coalesced global reads
        for (int e = tid; e < OT * ICB * 9; e += TPB) {
            int p  = e % 9;
            int ic = (e / 9) % ICB;
            int o  = e / (9 * ICB);
            int base = (((o0 + o) * C) + (ic0 + ic)) * 9 + p;
            float s = 0.f;
            #pragma unroll
            for (int k = 0; k < NK; k++)
                s = fmaf(sal[k], kern[k * (O * C * 9) + base], s);
            sw[ic][p][o] = s;
        }
        __syncthreads();

        // ---- compute ----
        #pragma unroll
        for (int ic = 0; ic < ICB; ic++) {
            #pragma unroll
            for (int kh = 0; kh < 3; kh++) {
                #pragma unroll
                for (int kw = 0; kw < 3; kw++) {
                    const ulonglong2* wp = (const ulonglong2*)&sw[ic][kh * 3 + kw][0];
                    ulonglong2 wa = wp[0];   // o pairs 0,1
                    ulonglong2 wb = wp[1];   // o pairs 2,3
                    #pragma unroll
                    for (int j = 0; j < 4; j++) {
                        float xs = sx[ic][ty + 4 * j + kh][tx + kw];
                        ull xv = pack2(xs, xs);
                        acc[j][0] = ffma2(wa.x, xv, acc[j][0]);
                        acc[j][1] = ffma2(wa.y, xv, acc[j][1]);
                        acc[j][2] = ffma2(wb.x, xv, acc[j][2]);
                        acc[j][3] = ffma2(wb.y, xv, acc[j][3]);
                    }
                }
            }
        }
        __syncthreads();
    }

    // ---- store ----
    #pragma unroll
    for (int j = 0; j < 4; j++) {
        int row = row0 + ty + 4 * j;
        if (row < HW) {
            #pragma unroll
            for (int q = 0; q < 4; q++) {
                float lo, hi;
                unpack2(acc[j][q], lo, hi);
                long base = (((long)b * O + (o0 + 2 * q)) * HW + row) * HW + tx;
                out[base] = lo;
                out[base + (long)HW * HW] = hi;
            }
        }
    }
}

extern "C" void kernel_launch(void* const* d_in, const int* in_sizes, int n_in,
                              void* d_out, int out_size) {
    const float* x    = (const float*)d_in[0];
    const float* kern = (const float*)d_in[1];
    const float* w1   = (const float*)d_in[2];
    const float* b1   = (const float*)d_in[3];
    const float* w2   = (const float*)d_in[4];
    const float* b2   = (const float*)d_in[5];
    float* out = (float*)d_out;

    pool_kernel<<<dim3(C, B), 256>>>(x);
    mlp_kernel<<<1, 256>>>(w1, b1, w2, b2);
    dim3 grid((HW + ROWS - 1) / ROWS, O / OT, B);   // 4 x 32 x 16
    dim3 block(HW, 4);                               // 224 threads
    conv_kernel<<<grid, block>>>(x, kern, out);
}

// round 4
// speedup vs baseline: 5.1098x; 4.2532x over previous
#include <cuda_runtime.h>
#include <cuda_bf16.h>
#include <cstdint>

// ---------------- dims ----------------
#define B_    16
#define C_    256
#define O_    256
#define HW_   56
#define NPIX  3136
#define NK    8
#define HID   64
#define KTOT  2304
#define NKEL  589824
#define PSTR  3264          // NPIX + 128 (64 guard each side)
#define GUARD 64

#define KC     32
#define NCHUNK 72           // 8 ic-groups * 9 taps
#define GRIDX  25           // ceil(3136/128) pix tiles

// smem element offsets (bf16 units)
#define SW_ROW   40         // 32 k + 8 pad
#define SX_ROW   136        // 128 pix + 8 pad
#define SW_HALF  (128 * SW_ROW)               // 5120
#define SX_HALF  (32 * SX_ROW)                // 4352
#define SW_ELEMS (2 * 2 * SW_HALF)            // 20480
#define SX_ELEMS (2 * 2 * SX_HALF)            // 17408
#define SMEM_BYTES ((SW_ELEMS + SX_ELEMS) * 2) // 75776? no: (20480+17408)*2 = 75776
// NOTE: actual = 2*(20480+17408) = 75776 bytes

__device__ float g_pooled[B_ * C_];
__device__ float g_alphas[B_ * NK];
__device__ __align__(16) unsigned short g_wmix[(size_t)B_ * 2 * O_ * KTOT];
// x split: [b][half][dwi][ic] planes of PSTR bf16 (+64 tail pad)
#define NPLANES ((size_t)B_ * 2 * 3 * C_)
__device__ __align__(16) unsigned short g_xs[NPLANES * PSTR + 64];

// ---------------- asm helpers ----------------
__device__ __forceinline__ uint32_t smem_u32(const void* p) {
    uint32_t a;
    asm("{ .reg .u64 t; cvta.to.shared.u64 t, %1; cvt.u32.u64 %0, t; }" : "=r"(a) : "l"(p));
    return a;
}
#define CP16(dst, src) asm volatile("cp.async.cg.shared.global [%0], [%1], 16;" :: "r"(dst), "l"(src))
#define CP_COMMIT()    asm volatile("cp.async.commit_group;" ::: "memory")
#define CP_WAIT(n)     asm volatile("cp.async.wait_group %0;" :: "n"(n) : "memory")

__device__ __forceinline__ void ldsm4(uint32_t* r, uint32_t a) {
    asm volatile("ldmatrix.sync.aligned.m8n8.x4.shared.b16 {%0,%1,%2,%3}, [%4];"
                 : "=r"(r[0]), "=r"(r[1]), "=r"(r[2]), "=r"(r[3]) : "r"(a));
}
__device__ __forceinline__ void ldsm4t(uint32_t* r, uint32_t a) {
    asm volatile("ldmatrix.sync.aligned.m8n8.x4.trans.shared.b16 {%0,%1,%2,%3}, [%4];"
                 : "=r"(r[0]), "=r"(r[1]), "=r"(r[2]), "=r"(r[3]) : "r"(a));
}
__device__ __forceinline__ void mma_bf16(float* d, const uint32_t* a, const uint32_t* b) {
    asm volatile("mma.sync.aligned.m16n8k16.row.col.f32.bf16.bf16.f32 "
                 "{%0,%1,%2,%3}, {%4,%5,%6,%7}, {%8,%9}, {%0,%1,%2,%3};"
                 : "+f"(d[0]), "+f"(d[1]), "+f"(d[2]), "+f"(d[3])
                 : "r"(a[0]), "r"(a[1]), "r"(a[2]), "r"(a[3]), "r"(b[0]), "r"(b[1]));
}

// ---------------- Kernel 1: x split (+pool fused) ----------------
__global__ void split_pool_kernel(const float* __restrict__ x) {
    const int ic = blockIdx.x, b = blockIdx.y;
    __shared__ float sp[NPIX];
    __shared__ float red[8];
    const float* xp = x + ((size_t)(b * C_ + ic)) * NPIX;
    float s = 0.f;
    for (int p = threadIdx.x; p < NPIX; p += 256) { float v = xp[p]; sp[p] = v; s += v; }
    #pragma unroll
    for (int o = 16; o > 0; o >>= 1) s += __shfl_xor_sync(0xffffffffu, s, o);
    if ((threadIdx.x & 31) == 0) red[threadIdx.x >> 5] = s;
    __syncthreads();
    if (threadIdx.x < 8) {
        s = red[threadIdx.x];
        #pragma unroll
        for (int o = 4; o > 0; o >>= 1) s += __shfl_xor_sync(0xffu, s, o);
        if (threadIdx.x == 0) g_pooled[b * C_ + ic] = s * (1.0f / NPIX);
    }
    // planes
    for (int p = threadIdx.x; p < NPIX; p += 256) {
        int h = p / HW_;
        int w = p - h * HW_;
        #pragma unroll
        for (int dwi = 0; dwi < 3; dwi++) {
            int ww = w + dwi - 1;
            float v = (ww >= 0 && ww < HW_) ? sp[p + dwi - 1] : 0.f;
            __nv_bfloat16 hb = __float2bfloat16(v);
            __nv_bfloat16 lb = __float2bfloat16(v - __bfloat162float(hb));
            g_xs[(size_t)(((b * 2 + 0) * 3 + dwi) * C_ + ic) * PSTR + GUARD + p] = __bfloat16_as_ushort(hb);
            g_xs[(size_t)(((b * 2 + 1) * 3 + dwi) * C_ + ic) * PSTR + GUARD + p] = __bfloat16_as_ushort(lb);
        }
    }
    // zero guards (front 64, back 64) for this (b, ic) across half x dwi
    for (int g = threadIdx.x; g < 768; g += 256) {
        int half = g / 384, r = g % 384, dwi = r / 128, q = r % 128;
        int pos = (q < 64) ? q : (PSTR - 128 + q);
        g_xs[(size_t)(((b * 2 + half) * 3 + dwi) * C_ + ic) * PSTR + pos] = 0;
    }
    if (b == 0 && ic == 0 && threadIdx.x < 64)
        g_xs[NPLANES * PSTR + threadIdx.x] = 0;   // tail pad
}

// ---------------- Kernel 2: MLP + softmax ----------------
__global__ void mlp_kernel(const float* __restrict__ w1, const float* __restrict__ b1,
                           const float* __restrict__ w2, const float* __restrict__ b2) {
    __shared__ float sp[B_ * C_];
    __shared__ float sh[B_ * HID];
    __shared__ float sc[B_ * NK];
    int tid = threadIdx.x;
    for (int i = tid; i < B_ * C_; i += 256) sp[i] = g_pooled[i];
    __syncthreads();
    for (int t = tid; t < B_ * HID; t += 256) {
        int b = t >> 6, j = t & 63;
        float s = b1[j];
        #pragma unroll 8
        for (int c = 0; c < C_; c++) s = fmaf(sp[b * C_ + c], w1[c * HID + j], s);
        sh[t] = fmaxf(s, 0.f);
    }
    __syncthreads();
    if (tid < B_ * NK) {
        int b = tid >> 3, k = tid & 7;
        float s = b2[k];
        #pragma unroll
        for (int j = 0; j < HID; j++) s = fmaf(sh[b * HID + j], w2[j * NK + k], s);
        sc[tid] = s;
    }
    __syncthreads();
    if (tid < B_) {
        float m = -1e30f;
        #pragma unroll
        for (int k = 0; k < NK; k++) m = fmaxf(m, sc[tid * NK + k]);
        float e[NK], sum = 0.f;
        #pragma unroll
        for (int k = 0; k < NK; k++) { e[k] = __expf(sc[tid * NK + k] - m); sum += e[k]; }
        float inv = 1.0f / sum;
        #pragma unroll
        for (int k = 0; k < NK; k++) g_alphas[tid * NK + k] = e[k] * inv;
    }
}

// ---------------- Kernel 3: weight mixing -> bf16 hi/lo ----------------
__global__ void mix_kernel(const float* __restrict__ kern) {
    __shared__ float sal[B_ * NK];
    if (threadIdx.x < B_ * NK) sal[threadIdx.x] = g_alphas[threadIdx.x];
    __syncthreads();
    int e = blockIdx.x * 256 + threadIdx.x;       // < 589824
    int o = e / KTOT;
    int kp = e - o * KTOT;
    int tap = kp >> 8;
    int ic = kp & 255;
    int src = (o * C_ + ic) * 9 + tap;
    float v[NK];
    #pragma unroll
    for (int k = 0; k < NK; k++) v[k] = kern[k * NKEL + src];
    #pragma unroll
    for (int b = 0; b < B_; b++) {
        float s = 0.f;
        #pragma unroll
        for (int k = 0; k < NK; k++) s = fmaf(sal[b * NK + k], v[k], s);
        __nv_bfloat16 hb = __float2bfloat16(s);
        __nv_bfloat16 lb = __float2bfloat16(s - __bfloat162float(hb));
        g_wmix[((size_t)(b * 2 + 0) * O_ + o) * KTOT + kp] = __bfloat16_as_ushort(hb);
        g_wmix[((size_t)(b * 2 + 1) * O_ + o) * KTOT + kp] = __bfloat16_as_ushort(lb);
    }
}

// ---------------- Kernel 4: implicit-GEMM conv via mma.sync ----------------
// Block: 256 thr, tile o128 x pix128. mma M=o, N=pix. 72 K-chunks of 32, double-buffered.
extern __shared__ __align__(16) unsigned short dynsm[];   // sW[2][2][128][40] then sX[2][2][32][136]

__global__ void __launch_bounds__(256, 2)
conv_kernel(float* __restrict__ out) {
    const int tid = threadIdx.x;
    const int n0 = blockIdx.x * 128;      // pix base
    const int o0 = blockIdx.y * 128;      // o base
    const int bb = blockIdx.z;

    const int warp = tid >> 5, L = tid & 31;
    const int wo = (warp >> 2) << 6;      // 0 / 64
    const int wp = (warp & 3) << 5;       // 0/32/64/96
    const int gid = L >> 2, tid4 = L & 3;

    const uint32_t sbase = smem_u32(dynsm);
    // per-lane ldmatrix row/col components
    const int aRow = wo + (L & 15);
    const int aCol = (L >> 4) << 3;           // 0/8
    const int xRow = L & 15;
    const int xCol = wp + ((L >> 4) << 3);

    // cp.async per-thread decode (4 W + 4 X items)
    int wHalf[4], wRowR[4], wJ[4];
    int xHalf[4], xKK[4], xJ[4];
    #pragma unroll
    for (int i = 0; i < 4; i++) {
        int e = tid + i * 256;
        wHalf[i] = e >> 9; wRowR[i] = (e >> 2) & 127; wJ[i] = e & 3;
        xHalf[i] = e >> 9; xKK[i] = (e >> 4) & 31; xJ[i] = e & 15;
    }

    float acc[4][4][4];
    #pragma unroll
    for (int mt = 0; mt < 4; mt++)
        #pragma unroll
        for (int nt = 0; nt < 4; nt++)
            #pragma unroll
            for (int r = 0; r < 4; r++) acc[mt][nt][r] = 0.f;

    // ---- chunk loader ----
    auto load_chunk = [&](int c, int bf) {
        int icg = c / 9;
        int tap = c - icg * 9;
        int dwi = tap % 3;
        int dh56 = (tap / 3 - 1) * HW_;
        #pragma unroll
        for (int i = 0; i < 4; i++) {
            // W
            const unsigned short* srcw = g_wmix
                + ((size_t)((bb * 2 + wHalf[i]) * O_ + o0 + wRowR[i])) * KTOT
                + tap * 256 + icg * 32 + wJ[i] * 8;
            uint32_t dstw = sbase + 2u * (((wHalf[i] + bf * 2) * 128 + wRowR[i]) * SW_ROW + wJ[i] * 8);
            CP16(dstw, srcw);
            // X
            size_t plane = (size_t)(((bb * 2 + xHalf[i]) * 3 + dwi) * C_ + icg * 32 + xKK[i]);
            const unsigned short* srcx = g_xs + plane * PSTR + GUARD + n0 + dh56 + xJ[i] * 8;
            uint32_t dstx = sbase + 2u * (SW_ELEMS + ((xHalf[i] + bf * 2) * 32 + xKK[i]) * SX_ROW + xJ[i] * 8);
            CP16(dstx, srcx);
        }
    };

    load_chunk(0, 0);
    CP_COMMIT();

    int bf = 0;
    for (int c = 0; c < NCHUNK; c++) {
        if (c + 1 < NCHUNK) {
            load_chunk(c + 1, bf ^ 1);
            CP_COMMIT();
            CP_WAIT(1);
        } else {
            CP_WAIT(0);
        }
        __syncthreads();

        // compute on buffer bf
        #pragma unroll
        for (int ks = 0; ks < 2; ks++) {
            uint32_t A[4][4], Bh[2][4], Bl[2][4];
            // W hi frags
            #pragma unroll
            for (int mt = 0; mt < 4; mt++) {
                uint32_t a = sbase + 2u * (((0 + bf * 2) * 128 + aRow + mt * 16) * SW_ROW + ks * 16 + aCol);
                ldsm4(A[mt], a);
            }
            // X hi frags
            #pragma unroll
            for (int np = 0; np < 2; np++) {
                uint32_t a = sbase + 2u * (SW_ELEMS + ((0 + bf * 2) * 32 + ks * 16 + xRow) * SX_ROW + xCol + np * 16);
                ldsm4t(Bh[np], a);
            }
            #pragma unroll
            for (int mt = 0; mt < 4; mt++)
                #pragma unroll
                for (int nt = 0; nt < 4; nt++)
                    mma_bf16(acc[mt][nt], A[mt], &Bh[nt >> 1][(nt & 1) * 2]);
            // X lo frags -> Whi * Xlo
            #pragma unroll
            for (int np = 0; np < 2; np++) {
                uint32_t a = sbase + 2u * (SW_ELEMS + ((1 + bf * 2) * 32 + ks * 16 + xRow) * SX_ROW + xCol + np * 16);
                ldsm4t(Bl[np], a);
            }
            #pragma unroll
            for (int mt = 0; mt < 4; mt++)
                #pragma unroll
                for (int nt = 0; nt < 4; nt++)
                    mma_bf16(acc[mt][nt], A[mt], &Bl[nt >> 1][(nt & 1) * 2]);
            // W lo frags -> Wlo * Xhi
            #pragma unroll
            for (int mt = 0; mt < 4; mt++) {
                uint32_t a = sbase + 2u * (((1 + bf * 2) * 128 + aRow + mt * 16) * SW_ROW + ks * 16 + aCol);
                ldsm4(A[mt], a);
            }
            #pragma unroll
            for (int mt = 0; mt < 4; mt++)
                #pragma unroll
                for (int nt = 0; nt < 4; nt++)
                    mma_bf16(acc[mt][nt], A[mt], &Bh[nt >> 1][(nt & 1) * 2]);
        }
        __syncthreads();
        bf ^= 1;
    }

    // ---- epilogue ----
    #pragma unroll
    for (int mt = 0; mt < 4; mt++) {
        #pragma unroll
        for (int nt = 0; nt < 4; nt++) {
            int o = o0 + wo + mt * 16 + gid;
            int pix = n0 + wp + nt * 8 + tid4 * 2;
            if (pix < NPIX) {
                size_t base = ((size_t)(bb * O_ + o)) * NPIX + pix;
                float2 v0 = make_float2(acc[mt][nt][0], acc[mt][nt][1]);
                float2 v1 = make_float2(acc[mt][nt][2], acc[mt][nt][3]);
                *(float2*)&out[base] = v0;
                *(float2*)&out[base + (size_t)8 * NPIX] = v1;
            }
        }
    }
}

extern "C" void kernel_launch(void* const* d_in, const int* in_sizes, int n_in,
                              void* d_out, int out_size) {
    const float* x    = (const float*)d_in[0];
    const float* kern = (const float*)d_in[1];
    const float* w1   = (const float*)d_in[2];
    const float* b1   = (const float*)d_in[3];
    const float* w2   = (const float*)d_in[4];
    const float* b2   = (const float*)d_in[5];
    float* out = (float*)d_out;

    static bool attr_set = false;
    const int smem_bytes = (SW_ELEMS + SX_ELEMS) * 2;   // 75776
    cudaFuncSetAttribute(conv_kernel, cudaFuncAttributeMaxDynamicSharedMemorySize, smem_bytes);
    (void)attr_set;

    split_pool_kernel<<<dim3(C_, B_), 256>>>(x);
    mlp_kernel<<<1, 256>>>(w1, b1, w2, b2);
    mix_kernel<<<NKEL / 256, 256>>>(kern);
    conv_kernel<<<dim3(GRIDX, 2, B_), 256, smem_bytes>>>(out);
}

// round 5
// speedup vs baseline: 5.2326x; 1.0240x over previous
#include <cuda_runtime.h>
#include <cuda_bf16.h>
#include <cstdint>

// ---------------- dims ----------------
#define B_    16
#define C_    256
#define O_    256
#define HW_   56
#define NPIX  3136
#define NK    8
#define HID   64
#define KTOT  2304
#define NKEL  589824
#define PSTR  3264          // NPIX + 128 (64 guard each side)
#define GUARD 64

#define KC     32
#define NCHUNK 72           // 8 ic-groups * 9 taps
#define GRIDX  25           // ceil(3136/128) pix tiles
#define NSTG   3

// smem element offsets (bf16 units)
#define SW_ROW   40         // 32 k + 8 pad
#define SX_ROW   136        // 128 pix + 8 pad
#define SW_STG   (2 * 128 * SW_ROW)           // 10240 elems (hi+lo W)
#define SX_STG   (2 * 32 * SX_ROW)            // 8704 elems (hi+lo X)
#define STG_ELEMS (SW_STG + SX_STG)           // 18944
#define SMEM_BYTES (NSTG * STG_ELEMS * 2)     // 113664

__device__ float g_pooled[B_ * C_];
__device__ float g_alphas[B_ * NK];
__device__ __align__(16) unsigned short g_wmix[(size_t)B_ * 2 * O_ * KTOT];
#define NPLANES ((size_t)B_ * 2 * 3 * C_)
__device__ __align__(16) unsigned short g_xs[NPLANES * PSTR + 64];

// ---------------- asm helpers ----------------
__device__ __forceinline__ uint32_t smem_u32(const void* p) {
    uint32_t a;
    asm("{ .reg .u64 t; cvta.to.shared.u64 t, %1; cvt.u32.u64 %0, t; }" : "=r"(a) : "l"(p));
    return a;
}
#define CP16(dst, src) asm volatile("cp.async.cg.shared.global [%0], [%1], 16;" :: "r"(dst), "l"(src))
#define CP_COMMIT()    asm volatile("cp.async.commit_group;" ::: "memory")
#define CP_WAIT(n)     asm volatile("cp.async.wait_group %0;" :: "n"(n) : "memory")

__device__ __forceinline__ void ldsm4(uint32_t* r, uint32_t a) {
    asm volatile("ldmatrix.sync.aligned.m8n8.x4.shared.b16 {%0,%1,%2,%3}, [%4];"
                 : "=r"(r[0]), "=r"(r[1]), "=r"(r[2]), "=r"(r[3]) : "r"(a));
}
__device__ __forceinline__ void ldsm4t(uint32_t* r, uint32_t a) {
    asm volatile("ldmatrix.sync.aligned.m8n8.x4.trans.shared.b16 {%0,%1,%2,%3}, [%4];"
                 : "=r"(r[0]), "=r"(r[1]), "=r"(r[2]), "=r"(r[3]) : "r"(a));
}
__device__ __forceinline__ void mma_bf16(float* d, const uint32_t* a, const uint32_t* b) {
    asm volatile("mma.sync.aligned.m16n8k16.row.col.f32.bf16.bf16.f32 "
                 "{%0,%1,%2,%3}, {%4,%5,%6,%7}, {%8,%9}, {%0,%1,%2,%3};"
                 : "+f"(d[0]), "+f"(d[1]), "+f"(d[2]), "+f"(d[3])
                 : "r"(a[0]), "r"(a[1]), "r"(a[2]), "r"(a[3]), "r"(b[0]), "r"(b[1]));
}

// ---------------- Kernel 1: x split (+pool fused) ----------------
__global__ void split_pool_kernel(const float* __restrict__ x) {
    const int ic = blockIdx.x, b = blockIdx.y;
    __shared__ float sp[NPIX];
    __shared__ float red[8];
    const float* xp = x + ((size_t)(b * C_ + ic)) * NPIX;
    float s = 0.f;
    for (int p = threadIdx.x; p < NPIX; p += 256) { float v = xp[p]; sp[p] = v; s += v; }
    #pragma unroll
    for (int o = 16; o > 0; o >>= 1) s += __shfl_xor_sync(0xffffffffu, s, o);
    if ((threadIdx.x & 31) == 0) red[threadIdx.x >> 5] = s;
    __syncthreads();
    if (threadIdx.x < 8) {
        s = red[threadIdx.x];
        #pragma unroll
        for (int o = 4; o > 0; o >>= 1) s += __shfl_xor_sync(0xffu, s, o);
        if (threadIdx.x == 0) g_pooled[b * C_ + ic] = s * (1.0f / NPIX);
    }
    for (int p = threadIdx.x; p < NPIX; p += 256) {
        int h = p / HW_;
        int w = p - h * HW_;
        #pragma unroll
        for (int dwi = 0; dwi < 3; dwi++) {
            int ww = w + dwi - 1;
            float v = (ww >= 0 && ww < HW_) ? sp[p + dwi - 1] : 0.f;
            __nv_bfloat16 hb = __float2bfloat16(v);
            __nv_bfloat16 lb = __float2bfloat16(v - __bfloat162float(hb));
            g_xs[(size_t)(((b * 2 + 0) * 3 + dwi) * C_ + ic) * PSTR + GUARD + p] = __bfloat16_as_ushort(hb);
            g_xs[(size_t)(((b * 2 + 1) * 3 + dwi) * C_ + ic) * PSTR + GUARD + p] = __bfloat16_as_ushort(lb);
        }
    }
    for (int g = threadIdx.x; g < 768; g += 256) {
        int half = g / 384, r = g % 384, dwi = r / 128, q = r % 128;
        int pos = (q < 64) ? q : (PSTR - 128 + q);
        g_xs[(size_t)(((b * 2 + half) * 3 + dwi) * C_ + ic) * PSTR + pos] = 0;
    }
    if (b == 0 && ic == 0 && threadIdx.x < 64)
        g_xs[NPLANES * PSTR + threadIdx.x] = 0;
}

// ---------------- Kernel 2: MLP + softmax ----------------
__global__ void mlp_kernel(const float* __restrict__ w1, const float* __restrict__ b1,
                           const float* __restrict__ w2, const float* __restrict__ b2) {
    __shared__ float sp[B_ * C_];
    __shared__ float sh[B_ * HID];
    __shared__ float sc[B_ * NK];
    int tid = threadIdx.x;
    for (int i = tid; i < B_ * C_; i += 256) sp[i] = g_pooled[i];
    __syncthreads();
    for (int t = tid; t < B_ * HID; t += 256) {
        int b = t >> 6, j = t & 63;
        float s = b1[j];
        #pragma unroll 8
        for (int c = 0; c < C_; c++) s = fmaf(sp[b * C_ + c], w1[c * HID + j], s);
        sh[t] = fmaxf(s, 0.f);
    }
    __syncthreads();
    if (tid < B_ * NK) {
        int b = tid >> 3, k = tid & 7;
        float s = b2[k];
        #pragma unroll
        for (int j = 0; j < HID; j++) s = fmaf(sh[b * HID + j], w2[j * NK + k], s);
        sc[tid] = s;
    }
    __syncthreads();
    if (tid < B_) {
        float m = -1e30f;
        #pragma unroll
        for (int k = 0; k < NK; k++) m = fmaxf(m, sc[tid * NK + k]);
        float e[NK], sum = 0.f;
        #pragma unroll
        for (int k = 0; k < NK; k++) { e[k] = __expf(sc[tid * NK + k] - m); sum += e[k]; }
        float inv = 1.0f / sum;
        #pragma unroll
        for (int k = 0; k < NK; k++) g_alphas[tid * NK + k] = e[k] * inv;
    }
}

// ---------------- Kernel 3: weight mixing -> bf16 hi/lo ----------------
__global__ void mix_kernel(const float* __restrict__ kern) {
    __shared__ float sal[B_ * NK];
    if (threadIdx.x < B_ * NK) sal[threadIdx.x] = g_alphas[threadIdx.x];
    __syncthreads();
    int e = blockIdx.x * 256 + threadIdx.x;
    int o = e / KTOT;
    int kp = e - o * KTOT;
    int tap = kp >> 8;
    int ic = kp & 255;
    int src = (o * C_ + ic) * 9 + tap;
    float v[NK];
    #pragma unroll
    for (int k = 0; k < NK; k++) v[k] = kern[k * NKEL + src];
    #pragma unroll
    for (int b = 0; b < B_; b++) {
        float s = 0.f;
        #pragma unroll
        for (int k = 0; k < NK; k++) s = fmaf(sal[b * NK + k], v[k], s);
        __nv_bfloat16 hb = __float2bfloat16(s);
        __nv_bfloat16 lb = __float2bfloat16(s - __bfloat162float(hb));
        g_wmix[((size_t)(b * 2 + 0) * O_ + o) * KTOT + kp] = __bfloat16_as_ushort(hb);
        g_wmix[((size_t)(b * 2 + 1) * O_ + o) * KTOT + kp] = __bfloat16_as_ushort(lb);
    }
}

// ---------------- Kernel 4: implicit-GEMM conv via mma.sync ----------------
// 256 thr, tile o128 x pix128, 72 K-chunks of 32, 3-stage cp.async pipeline,
// ONE __syncthreads per chunk.
extern __shared__ __align__(16) unsigned short dynsm[];

__global__ void __launch_bounds__(256, 2)
conv_kernel(float* __restrict__ out) {
    const int tid = threadIdx.x;
    const int n0 = blockIdx.x * 128;
    const int o0 = blockIdx.y * 128;
    const int bb = blockIdx.z;

    const int warp = tid >> 5, L = tid & 31;
    const int wo = (warp >> 2) << 6;
    const int wp = (warp & 3) << 5;
    const int gid = L >> 2, tid4 = L & 3;

    const uint32_t sbase = smem_u32(dynsm);
    const int aRow = wo + (L & 15);
    const int aCol = (L >> 4) << 3;
    const int xRow = L & 15;
    const int xCol = wp + ((L >> 4) << 3);

    int wHalf[4], wRowR[4], wJ[4];
    int xHalf[4], xKK[4], xJ[4];
    #pragma unroll
    for (int i = 0; i < 4; i++) {
        int e = tid + i * 256;
        wHalf[i] = e >> 9; wRowR[i] = (e >> 2) & 127; wJ[i] = e & 3;
        xHalf[i] = e >> 9; xKK[i] = (e >> 4) & 31; xJ[i] = e & 15;
    }

    float acc[4][4][4];
    #pragma unroll
    for (int mt = 0; mt < 4; mt++)
        #pragma unroll
        for (int nt = 0; nt < 4; nt++)
            #pragma unroll
            for (int r = 0; r < 4; r++) acc[mt][nt][r] = 0.f;

    auto load_chunk = [&](int c, int stg) {
        int icg = c / 9;
        int tap = c - icg * 9;
        int dwi = tap % 3;
        int dh56 = (tap / 3 - 1) * HW_;
        uint32_t sb = sbase + (uint32_t)stg * (STG_ELEMS * 2);
        #pragma unroll
        for (int i = 0; i < 4; i++) {
            const unsigned short* srcw = g_wmix
                + ((size_t)((bb * 2 + wHalf[i]) * O_ + o0 + wRowR[i])) * KTOT
                + tap * 256 + icg * 32 + wJ[i] * 8;
            uint32_t dstw = sb + 2u * ((wHalf[i] * 128 + wRowR[i]) * SW_ROW + wJ[i] * 8);
            CP16(dstw, srcw);
            size_t plane = (size_t)(((bb * 2 + xHalf[i]) * 3 + dwi) * C_ + icg * 32 + xKK[i]);
            const unsigned short* srcx = g_xs + plane * PSTR + GUARD + n0 + dh56 + xJ[i] * 8;
            uint32_t dstx = sb + 2u * (SW_STG + (xHalf[i] * 32 + xKK[i]) * SX_ROW + xJ[i] * 8);
            CP16(dstx, srcx);
        }
    };

    load_chunk(0, 0); CP_COMMIT();
    load_chunk(1, 1); CP_COMMIT();

    int stage = 0;
    for (int c = 0; c < NCHUNK; c++) {
        if (c < NCHUNK - 1) { CP_WAIT(1); } else { CP_WAIT(0); }
        __syncthreads();
        if (c + 2 < NCHUNK) {
            int s2 = stage + 2; if (s2 >= NSTG) s2 -= NSTG;
            load_chunk(c + 2, s2);
            CP_COMMIT();
        }

        const uint32_t sb = sbase + (uint32_t)stage * (STG_ELEMS * 2);
        #pragma unroll
        for (int ks = 0; ks < 2; ks++) {
            uint32_t A[4][4], Bh[2][4], Bl[2][4];
            #pragma unroll
            for (int mt = 0; mt < 4; mt++) {
                uint32_t a = sb + 2u * ((0 * 128 + aRow + mt * 16) * SW_ROW + ks * 16 + aCol);
                ldsm4(A[mt], a);
            }
            #pragma unroll
            for (int np = 0; np < 2; np++) {
                uint32_t a = sb + 2u * (SW_STG + (0 * 32 + ks * 16 + xRow) * SX_ROW + xCol + np * 16);
                ldsm4t(Bh[np], a);
            }
            #pragma unroll
            for (int mt = 0; mt < 4; mt++)
                #pragma unroll
                for (int nt = 0; nt < 4; nt++)
                    mma_bf16(acc[mt][nt], A[mt], &Bh[nt >> 1][(nt & 1) * 2]);
            #pragma unroll
            for (int np = 0; np < 2; np++) {
                uint32_t a = sb + 2u * (SW_STG + (1 * 32 + ks * 16 + xRow) * SX_ROW + xCol + np * 16);
                ldsm4t(Bl[np], a);
            }
            #pragma unroll
            for (int mt = 0; mt < 4; mt++)
                #pragma unroll
                for (int nt = 0; nt < 4; nt++)
                    mma_bf16(acc[mt][nt], A[mt], &Bl[nt >> 1][(nt & 1) * 2]);
            #pragma unroll
            for (int mt = 0; mt < 4; mt++) {
                uint32_t a = sb + 2u * ((1 * 128 + aRow + mt * 16) * SW_ROW + ks * 16 + aCol);
                ldsm4(A[mt], a);
            }
            #pragma unroll
            for (int mt = 0; mt < 4; mt++)
                #pragma unroll
                for (int nt = 0; nt < 4; nt++)
                    mma_bf16(acc[mt][nt], A[mt], &Bh[nt >> 1][(nt & 1) * 2]);
        }
        stage = stage + 1; if (stage >= NSTG) stage -= NSTG;
    }

    #pragma unroll
    for (int mt = 0; mt < 4; mt++) {
        #pragma unroll
        for (int nt = 0; nt < 4; nt++) {
            int o = o0 + wo + mt * 16 + gid;
            int pix = n0 + wp + nt * 8 + tid4 * 2;
            if (pix < NPIX) {
                size_t base = ((size_t)(bb * O_ + o)) * NPIX + pix;
                *(float2*)&out[base] = make_float2(acc[mt][nt][0], acc[mt][nt][1]);
                *(float2*)&out[base + (size_t)8 * NPIX] = make_float2(acc[mt][nt][2], acc[mt][nt][3]);
            }
        }
    }
}

extern "C" void kernel_launch(void* const* d_in, const int* in_sizes, int n_in,
                              void* d_out, int out_size) {
    const float* x    = (const float*)d_in[0];
    const float* kern = (const float*)d_in[1];
    const float* w1   = (const float*)d_in[2];
    const float* b1   = (const float*)d_in[3];
    const float* w2   = (const float*)d_in[4];
    const float* b2   = (const float*)d_in[5];
    float* out = (float*)d_out;

    cudaFuncSetAttribute(conv_kernel, cudaFuncAttributeMaxDynamicSharedMemorySize, SMEM_BYTES);

    split_pool_kernel<<<dim3(C_, B_), 256>>>(x);
    mlp_kernel<<<1, 256>>>(w1, b1, w2, b2);
    mix_kernel<<<NKEL / 256, 256>>>(kern);
    conv_kernel<<<dim3(GRIDX, 2, B_), 256, SMEM_BYTES>>>(out);
}

// round 6
// speedup vs baseline: 6.8886x; 1.3165x over previous
#include <cuda_runtime.h>
#include <cuda_bf16.h>
#include <cuda_fp16.h>
#include <cstdint>

// ---------------- dims ----------------
#define B_    16
#define C_    256
#define O_    256
#define HW_   56
#define NPIX  3136
#define NK    8
#define HID   64
#define KTOT  2304
#define NKEL  589824
#define PSTR  3264          // NPIX + 128 (64 guard each side)
#define GUARD 64

#define KC     32
#define NCHUNK 72           // 8 ic-groups * 9 taps
#define GRIDX  25           // ceil(3136/128) pix tiles
#define NSTG   3

// smem element offsets (fp16 units)
#define SW_ROW   40         // 32 k + 8 pad
#define SX_ROW   136        // 128 pix + 8 pad
#define SW_STG   (2 * 128 * SW_ROW)           // 10240 elems (hi+lo W)
#define SX_STG   (32 * SX_ROW)                // 4352 elems (single X)
#define STG_ELEMS (SW_STG + SX_STG)           // 14592
#define SMEM_BYTES (NSTG * STG_ELEMS * 2)     // 87552

__device__ float g_pooled[B_ * C_];
__device__ float g_alphas[B_ * NK];
__device__ __align__(16) unsigned short g_wmix[(size_t)B_ * 2 * O_ * KTOT];
#define NPLANES ((size_t)B_ * 3 * C_)
__device__ __align__(16) unsigned short g_xs[NPLANES * PSTR + 64];

// ---------------- asm helpers ----------------
__device__ __forceinline__ uint32_t smem_u32(const void* p) {
    uint32_t a;
    asm("{ .reg .u64 t; cvta.to.shared.u64 t, %1; cvt.u32.u64 %0, t; }" : "=r"(a) : "l"(p));
    return a;
}
#define CP16(dst, src) asm volatile("cp.async.cg.shared.global [%0], [%1], 16;" :: "r"(dst), "l"(src))
#define CP_COMMIT()    asm volatile("cp.async.commit_group;" ::: "memory")
#define CP_WAIT(n)     asm volatile("cp.async.wait_group %0;" :: "n"(n) : "memory")

__device__ __forceinline__ void ldsm4(uint32_t* r, uint32_t a) {
    asm volatile("ldmatrix.sync.aligned.m8n8.x4.shared.b16 {%0,%1,%2,%3}, [%4];"
                 : "=r"(r[0]), "=r"(r[1]), "=r"(r[2]), "=r"(r[3]) : "r"(a));
}
__device__ __forceinline__ void ldsm4t(uint32_t* r, uint32_t a) {
    asm volatile("ldmatrix.sync.aligned.m8n8.x4.trans.shared.b16 {%0,%1,%2,%3}, [%4];"
                 : "=r"(r[0]), "=r"(r[1]), "=r"(r[2]), "=r"(r[3]) : "r"(a));
}
__device__ __forceinline__ void mma_f16(float* d, const uint32_t* a, const uint32_t* b) {
    asm volatile("mma.sync.aligned.m16n8k16.row.col.f32.f16.f16.f32 "
                 "{%0,%1,%2,%3}, {%4,%5,%6,%7}, {%8,%9}, {%0,%1,%2,%3};"
                 : "+f"(d[0]), "+f"(d[1]), "+f"(d[2]), "+f"(d[3])
                 : "r"(a[0]), "r"(a[1]), "r"(a[2]), "r"(a[3]), "r"(b[0]), "r"(b[1]));
}

// ---------------- Kernel 1: x -> fp16 planes (+pool fused) ----------------
__global__ void split_pool_kernel(const float* __restrict__ x) {
    const int ic = blockIdx.x, b = blockIdx.y;
    __shared__ float sp[NPIX];
    __shared__ float red[8];
    const float* xp = x + ((size_t)(b * C_ + ic)) * NPIX;
    float s = 0.f;
    for (int p = threadIdx.x; p < NPIX; p += 256) { float v = xp[p]; sp[p] = v; s += v; }
    #pragma unroll
    for (int o = 16; o > 0; o >>= 1) s += __shfl_xor_sync(0xffffffffu, s, o);
    if ((threadIdx.x & 31) == 0) red[threadIdx.x >> 5] = s;
    __syncthreads();
    if (threadIdx.x < 8) {
        s = red[threadIdx.x];
        #pragma unroll
        for (int o = 4; o > 0; o >>= 1) s += __shfl_xor_sync(0xffu, s, o);
        if (threadIdx.x == 0) g_pooled[b * C_ + ic] = s * (1.0f / NPIX);
    }
    for (int p = threadIdx.x; p < NPIX; p += 256) {
        int h = p / HW_;
        int w = p - h * HW_;
        #pragma unroll
        for (int dwi = 0; dwi < 3; dwi++) {
            int ww = w + dwi - 1;
            float v = (ww >= 0 && ww < HW_) ? sp[p + dwi - 1] : 0.f;
            __half hv = __float2half_rn(v);
            g_xs[(size_t)((b * 3 + dwi) * C_ + ic) * PSTR + GUARD + p] = __half_as_ushort(hv);
        }
    }
    for (int g = threadIdx.x; g < 384; g += 256) {
        int dwi = g / 128, q = g % 128;
        int pos = (q < 64) ? q : (PSTR - 128 + q);
        g_xs[(size_t)((b * 3 + dwi) * C_ + ic) * PSTR + pos] = 0;
    }
    if (b == 0 && ic == 0 && threadIdx.x < 64)
        g_xs[NPLANES * PSTR + threadIdx.x] = 0;
}

// ---------------- Kernel 2: MLP + softmax ----------------
__global__ void mlp_kernel(const float* __restrict__ w1, const float* __restrict__ b1,
                           const float* __restrict__ w2, const float* __restrict__ b2) {
    __shared__ float sp[B_ * C_];
    __shared__ float sh[B_ * HID];
    __shared__ float sc[B_ * NK];
    int tid = threadIdx.x;
    for (int i = tid; i < B_ * C_; i += 256) sp[i] = g_pooled[i];
    __syncthreads();
    for (int t = tid; t < B_ * HID; t += 256) {
        int b = t >> 6, j = t & 63;
        float s = b1[j];
        #pragma unroll 8
        for (int c = 0; c < C_; c++) s = fmaf(sp[b * C_ + c], w1[c * HID + j], s);
        sh[t] = fmaxf(s, 0.f);
    }
    __syncthreads();
    if (tid < B_ * NK) {
        int b = tid >> 3, k = tid & 7;
        float s = b2[k];
        #pragma unroll
        for (int j = 0; j < HID; j++) s = fmaf(sh[b * HID + j], w2[j * NK + k], s);
        sc[tid] = s;
    }
    __syncthreads();
    if (tid < B_) {
        float m = -1e30f;
        #pragma unroll
        for (int k = 0; k < NK; k++) m = fmaxf(m, sc[tid * NK + k]);
        float e[NK], sum = 0.f;
        #pragma unroll
        for (int k = 0; k < NK; k++) { e[k] = __expf(sc[tid * NK + k] - m); sum += e[k]; }
        float inv = 1.0f / sum;
        #pragma unroll
        for (int k = 0; k < NK; k++) g_alphas[tid * NK + k] = e[k] * inv;
    }
}

// ---------------- Kernel 3: weight mixing -> fp16 hi/lo ----------------
__global__ void mix_kernel(const float* __restrict__ kern) {
    __shared__ float sal[B_ * NK];
    if (threadIdx.x < B_ * NK) sal[threadIdx.x] = g_alphas[threadIdx.x];
    __syncthreads();
    int e = blockIdx.x * 256 + threadIdx.x;
    int o = e / KTOT;
    int kp = e - o * KTOT;
    int tap = kp >> 8;
    int ic = kp & 255;
    int src = (o * C_ + ic) * 9 + tap;
    float v[NK];
    #pragma unroll
    for (int k = 0; k < NK; k++) v[k] = kern[k * NKEL + src];
    #pragma unroll
    for (int b = 0; b < B_; b++) {
        float s = 0.f;
        #pragma unroll
        for (int k = 0; k < NK; k++) s = fmaf(sal[b * NK + k], v[k], s);
        __half hb = __float2half_rn(s);
        __half lb = __float2half_rn(s - __half2float(hb));
        g_wmix[((size_t)(b * 2 + 0) * O_ + o) * KTOT + kp] = __half_as_ushort(hb);
        g_wmix[((size_t)(b * 2 + 1) * O_ + o) * KTOT + kp] = __half_as_ushort(lb);
    }
}

// ---------------- Kernel 4: implicit-GEMM conv via mma.sync (fp16, 2-product) ----
extern __shared__ __align__(16) unsigned short dynsm[];

__global__ void __launch_bounds__(256, 2)
conv_kernel(float* __restrict__ out) {
    const int tid = threadIdx.x;
    const int n0 = blockIdx.x * 128;
    const int o0 = blockIdx.y * 128;
    const int bb = blockIdx.z;

    const int warp = tid >> 5, L = tid & 31;
    const int wo = (warp >> 2) << 6;
    const int wp = (warp & 3) << 5;
    const int gid = L >> 2, tid4 = L & 3;

    const uint32_t sbase = smem_u32(dynsm);
    const int aRow = wo + (L & 15);
    const int aCol = (L >> 4) << 3;
    const int xRow = L & 15;
    const int xCol = wp + ((L >> 4) << 3);

    int wHalf[4], wRowR[4], wJ[4];
    int xKK[2], xJ[2];
    #pragma unroll
    for (int i = 0; i < 4; i++) {
        int e = tid + i * 256;
        wHalf[i] = e >> 9; wRowR[i] = (e >> 2) & 127; wJ[i] = e & 3;
    }
    #pragma unroll
    for (int i = 0; i < 2; i++) {
        int e = tid + i * 256;
        xKK[i] = (e >> 4) & 31; xJ[i] = e & 15;
    }

    float acc[4][4][4];
    #pragma unroll
    for (int mt = 0; mt < 4; mt++)
        #pragma unroll
        for (int nt = 0; nt < 4; nt++)
            #pragma unroll
            for (int r = 0; r < 4; r++) acc[mt][nt][r] = 0.f;

    auto load_chunk = [&](int c, int stg) {
        int icg = c / 9;
        int tap = c - icg * 9;
        int dwi = tap % 3;
        int dh56 = (tap / 3 - 1) * HW_;
        uint32_t sb = sbase + (uint32_t)stg * (STG_ELEMS * 2);
        #pragma unroll
        for (int i = 0; i < 4; i++) {
            const unsigned short* srcw = g_wmix
                + ((size_t)((bb * 2 + wHalf[i]) * O_ + o0 + wRowR[i])) * KTOT
                + tap * 256 + icg * 32 + wJ[i] * 8;
            uint32_t dstw = sb + 2u * ((wHalf[i] * 128 + wRowR[i]) * SW_ROW + wJ[i] * 8);
            CP16(dstw, srcw);
        }
        #pragma unroll
        for (int i = 0; i < 2; i++) {
            size_t plane = (size_t)((bb * 3 + dwi) * C_ + icg * 32 + xKK[i]);
            const unsigned short* srcx = g_xs + plane * PSTR + GUARD + n0 + dh56 + xJ[i] * 8;
            uint32_t dstx = sb + 2u * (SW_STG + xKK[i] * SX_ROW + xJ[i] * 8);
            CP16(dstx, srcx);
        }
    };

    load_chunk(0, 0); CP_COMMIT();
    load_chunk(1, 1); CP_COMMIT();

    int stage = 0;
    for (int c = 0; c < NCHUNK; c++) {
        if (c < NCHUNK - 1) { CP_WAIT(1); } else { CP_WAIT(0); }
        __syncthreads();
        if (c + 2 < NCHUNK) {
            int s2 = stage + 2; if (s2 >= NSTG) s2 -= NSTG;
            load_chunk(c + 2, s2);
            CP_COMMIT();
        }

        const uint32_t sb = sbase + (uint32_t)stage * (STG_ELEMS * 2);
        #pragma unroll
        for (int ks = 0; ks < 2; ks++) {
            uint32_t A[4][4], Bh[2][4];
            #pragma unroll
            for (int mt = 0; mt < 4; mt++) {
                uint32_t a = sb + 2u * ((0 * 128 + aRow + mt * 16) * SW_ROW + ks * 16 + aCol);
                ldsm4(A[mt], a);
            }
            #pragma unroll
            for (int np = 0; np < 2; np++) {
                uint32_t a = sb + 2u * (SW_STG + (ks * 16 + xRow) * SX_ROW + xCol + np * 16);
                ldsm4t(Bh[np], a);
            }
            #pragma unroll
            for (int mt = 0; mt < 4; mt++)
                #pragma unroll
                for (int nt = 0; nt < 4; nt++)
                    mma_f16(acc[mt][nt], A[mt], &Bh[nt >> 1][(nt & 1) * 2]);
            #pragma unroll
            for (int mt = 0; mt < 4; mt++) {
                uint32_t a = sb + 2u * ((1 * 128 + aRow + mt * 16) * SW_ROW + ks * 16 + aCol);
                ldsm4(A[mt], a);
            }
            #pragma unroll
            for (int mt = 0; mt < 4; mt++)
                #pragma unroll
                for (int nt = 0; nt < 4; nt++)
                    mma_f16(acc[mt][nt], A[mt], &Bh[nt >> 1][(nt & 1) * 2]);
        }
        stage = stage + 1; if (stage >= NSTG) stage -= NSTG;
    }

    #pragma unroll
    for (int mt = 0; mt < 4; mt++) {
        #pragma unroll
        for (int nt = 0; nt < 4; nt++) {
            int o = o0 + wo + mt * 16 + gid;
            int pix = n0 + wp + nt * 8 + tid4 * 2;
            if (pix < NPIX) {
                size_t base = ((size_t)(bb * O_ + o)) * NPIX + pix;
                *(float2*)&out[base] = make_float2(acc[mt][nt][0], acc[mt][nt][1]);
                *(float2*)&out[base + (size_t)8 * NPIX] = make_float2(acc[mt][nt][2], acc[mt][nt][3]);
            }
        }
    }
}

extern "C" void kernel_launch(void* const* d_in, const int* in_sizes, int n_in,
                              void* d_out, int out_size) {
    const float* x    = (const float*)d_in[0];
    const float* kern = (const float*)d_in[1];
    const float* w1   = (const float*)d_in[2];
    const float* b1   = (const float*)d_in[3];
    const float* w2   = (const float*)d_in[4];
    const float* b2   = (const float*)d_in[5];
    float* out = (float*)d_out;

    cudaFuncSetAttribute(conv_kernel, cudaFuncAttributeMaxDynamicSharedMemorySize, SMEM_BYTES);

    split_pool_kernel<<<dim3(C_, B_), 256>>>(x);
    mlp_kernel<<<1, 256>>>(w1, b1, w2, b2);
    mix_kernel<<<NKEL / 256, 256>>>(kern);
    conv_kernel<<<dim3(GRIDX, 2, B_), 256, SMEM_BYTES>>>(out);
}

// round 7
// speedup vs baseline: 11.1340x; 1.6163x over previous
#include <cuda_runtime.h>
#include <cuda_bf16.h>
#include <cuda_fp16.h>
#include <cstdint>

// ---------------- dims ----------------
#define B_    16
#define C_    256
#define O_    256
#define HW_   56
#define NPIX  3136
#define NK    8
#define HID   64
#define KTOT  2304
#define NKEL  589824
#define PSTR  3264          // NPIX + 128 (64 guard each side)
#define GUARD 64

#define KC     32
#define NCHUNK 72           // 8 ic-groups * 9 taps
#define GRIDX  25           // ceil(3136/128) pix tiles
#define NSTG   3

// smem element offsets (fp16 units)
#define SW_ROW   40         // 32 k + 8 pad
#define SX_ROW   136        // 128 pix + 8 pad
#define SW_STG   (128 * SW_ROW)               // 5120 elems (single W)
#define SX_STG   (32 * SX_ROW)                // 4352 elems (single X)
#define STG_ELEMS (SW_STG + SX_STG)           // 9472
#define SMEM_BYTES (NSTG * STG_ELEMS * 2)     // 56832

__device__ float g_pooled[B_ * C_];
__device__ float g_alphas[B_ * NK];
__device__ __align__(16) unsigned short g_wmix[(size_t)B_ * O_ * KTOT];
#define NPLANES ((size_t)B_ * 3 * C_)
__device__ __align__(16) unsigned short g_xs[NPLANES * PSTR + 64];

// ---------------- asm helpers ----------------
__device__ __forceinline__ uint32_t smem_u32(const void* p) {
    uint32_t a;
    asm("{ .reg .u64 t; cvta.to.shared.u64 t, %1; cvt.u32.u64 %0, t; }" : "=r"(a) : "l"(p));
    return a;
}
#define CP16(dst, src) asm volatile("cp.async.cg.shared.global [%0], [%1], 16;" :: "r"(dst), "l"(src))
#define CP_COMMIT()    asm volatile("cp.async.commit_group;" ::: "memory")
#define CP_WAIT(n)     asm volatile("cp.async.wait_group %0;" :: "n"(n) : "memory")

__device__ __forceinline__ void ldsm4(uint32_t* r, uint32_t a) {
    asm volatile("ldmatrix.sync.aligned.m8n8.x4.shared.b16 {%0,%1,%2,%3}, [%4];"
                 : "=r"(r[0]), "=r"(r[1]), "=r"(r[2]), "=r"(r[3]) : "r"(a));
}
__device__ __forceinline__ void ldsm4t(uint32_t* r, uint32_t a) {
    asm volatile("ldmatrix.sync.aligned.m8n8.x4.trans.shared.b16 {%0,%1,%2,%3}, [%4];"
                 : "=r"(r[0]), "=r"(r[1]), "=r"(r[2]), "=r"(r[3]) : "r"(a));
}
__device__ __forceinline__ void mma_f16(float* d, const uint32_t* a, const uint32_t* b) {
    asm volatile("mma.sync.aligned.m16n8k16.row.col.f32.f16.f16.f32 "
                 "{%0,%1,%2,%3}, {%4,%5,%6,%7}, {%8,%9}, {%0,%1,%2,%3};"
                 : "+f"(d[0]), "+f"(d[1]), "+f"(d[2]), "+f"(d[3])
                 : "r"(a[0]), "r"(a[1]), "r"(a[2]), "r"(a[3]), "r"(b[0]), "r"(b[1]));
}

// ---------------- Kernel 1: x -> fp16 planes (+pool fused) ----------------
__global__ void split_pool_kernel(const float* __restrict__ x) {
    const int ic = blockIdx.x, b = blockIdx.y;
    __shared__ float sp[NPIX];
    __shared__ float red[8];
    const float* xp = x + ((size_t)(b * C_ + ic)) * NPIX;
    float s = 0.f;
    for (int p = threadIdx.x; p < NPIX; p += 256) { float v = xp[p]; sp[p] = v; s += v; }
    #pragma unroll
    for (int o = 16; o > 0; o >>= 1) s += __shfl_xor_sync(0xffffffffu, s, o);
    if ((threadIdx.x & 31) == 0) red[threadIdx.x >> 5] = s;
    __syncthreads();
    if (threadIdx.x < 8) {
        s = red[threadIdx.x];
        #pragma unroll
        for (int o = 4; o > 0; o >>= 1) s += __shfl_xor_sync(0xffu, s, o);
        if (threadIdx.x == 0) g_pooled[b * C_ + ic] = s * (1.0f / NPIX);
    }
    for (int p = threadIdx.x; p < NPIX; p += 256) {
        int h = p / HW_;
        int w = p - h * HW_;
        #pragma unroll
        for (int dwi = 0; dwi < 3; dwi++) {
            int ww = w + dwi - 1;
            float v = (ww >= 0 && ww < HW_) ? sp[p + dwi - 1] : 0.f;
            __half hv = __float2half_rn(v);
            g_xs[(size_t)((b * 3 + dwi) * C_ + ic) * PSTR + GUARD + p] = __half_as_ushort(hv);
        }
    }
    for (int g = threadIdx.x; g < 384; g += 256) {
        int dwi = g / 128, q = g % 128;
        int pos = (q < 64) ? q : (PSTR - 128 + q);
        g_xs[(size_t)((b * 3 + dwi) * C_ + ic) * PSTR + pos] = 0;
    }
    if (b == 0 && ic == 0 && threadIdx.x < 64)
        g_xs[NPLANES * PSTR + threadIdx.x] = 0;
}

// ---------------- Kernel 2: MLP + softmax ----------------
__global__ void mlp_kernel(const float* __restrict__ w1, const float* __restrict__ b1,
                           const float* __restrict__ w2, const float* __restrict__ b2) {
    __shared__ float sp[B_ * C_];
    __shared__ float sh[B_ * HID];
    __shared__ float sc[B_ * NK];
    int tid = threadIdx.x;
    for (int i = tid; i < B_ * C_; i += 256) sp[i] = g_pooled[i];
    __syncthreads();
    for (int t = tid; t < B_ * HID; t += 256) {
        int b = t >> 6, j = t & 63;
        float s = b1[j];
        #pragma unroll 8
        for (int c = 0; c < C_; c++) s = fmaf(sp[b * C_ + c], w1[c * HID + j], s);
        sh[t] = fmaxf(s, 0.f);
    }
    __syncthreads();
    if (tid < B_ * NK) {
        int b = tid >> 3, k = tid & 7;
        float s = b2[k];
        #pragma unroll
        for (int j = 0; j < HID; j++) s = fmaf(sh[b * HID + j], w2[j * NK + k], s);
        sc[tid] = s;
    }
    __syncthreads();
    if (tid < B_) {
        float m = -1e30f;
        #pragma unroll
        for (int k = 0; k < NK; k++) m = fmaxf(m, sc[tid * NK + k]);
        float e[NK], sum = 0.f;
        #pragma unroll
        for (int k = 0; k < NK; k++) { e[k] = __expf(sc[tid * NK + k] - m); sum += e[k]; }
        float inv = 1.0f / sum;
        #pragma unroll
        for (int k = 0; k < NK; k++) g_alphas[tid * NK + k] = e[k] * inv;
    }
}

// ---------------- Kernel 3: weight mixing -> fp16 ----------------
__global__ void mix_kernel(const float* __restrict__ kern) {
    __shared__ float sal[B_ * NK];
    if (threadIdx.x < B_ * NK) sal[threadIdx.x] = g_alphas[threadIdx.x];
    __syncthreads();
    int e = blockIdx.x * 256 + threadIdx.x;
    int o = e / KTOT;
    int kp = e - o * KTOT;
    int tap = kp >> 8;
    int ic = kp & 255;
    int src = (o * C_ + ic) * 9 + tap;
    float v[NK];
    #pragma unroll
    for (int k = 0; k < NK; k++) v[k] = kern[k * NKEL + src];
    #pragma unroll
    for (int b = 0; b < B_; b++) {
        float s = 0.f;
        #pragma unroll
        for (int k = 0; k < NK; k++) s = fmaf(sal[b * NK + k], v[k], s);
        g_wmix[((size_t)b * O_ + o) * KTOT + kp] = __half_as_ushort(__float2half_rn(s));
    }
}

// ---------------- Kernel 4: implicit-GEMM conv via mma.sync (fp16, 1 product) ----
extern __shared__ __align__(16) unsigned short dynsm[];

__global__ void __launch_bounds__(256, 2)
conv_kernel(float* __restrict__ out) {
    const int tid = threadIdx.x;
    const int n0 = blockIdx.x * 128;
    const int o0 = blockIdx.y * 128;
    const int bb = blockIdx.z;

    const int warp = tid >> 5, L = tid & 31;
    const int wo = (warp >> 2) << 6;
    const int wp = (warp & 3) << 5;
    const int gid = L >> 2, tid4 = L & 3;

    const uint32_t sbase = smem_u32(dynsm);
    const int aRow = wo + (L & 15);
    const int aCol = (L >> 4) << 3;
    const int xRow = L & 15;
    const int xCol = wp + ((L >> 4) << 3);

    int wRowR[2], wJ[2], xKK[2], xJ[2];
    #pragma unroll
    for (int i = 0; i < 2; i++) {
        int e = tid + i * 256;
        wRowR[i] = (e >> 2) & 127; wJ[i] = e & 3;
        xKK[i] = (e >> 4) & 31; xJ[i] = e & 15;
    }

    float acc[4][4][4];
    #pragma unroll
    for (int mt = 0; mt < 4; mt++)
        #pragma unroll
        for (int nt = 0; nt < 4; nt++)
            #pragma unroll
            for (int r = 0; r < 4; r++) acc[mt][nt][r] = 0.f;

    auto load_chunk = [&](int c, int stg) {
        int icg = c / 9;
        int tap = c - icg * 9;
        int dwi = tap % 3;
        int dh56 = (tap / 3 - 1) * HW_;
        uint32_t sb = sbase + (uint32_t)stg * (STG_ELEMS * 2);
        #pragma unroll
        for (int i = 0; i < 2; i++) {
            const unsigned short* srcw = g_wmix
                + ((size_t)(bb * O_ + o0 + wRowR[i])) * KTOT
                + tap * 256 + icg * 32 + wJ[i] * 8;
            uint32_t dstw = sb + 2u * (wRowR[i] * SW_ROW + wJ[i] * 8);
            CP16(dstw, srcw);
            size_t plane = (size_t)((bb * 3 + dwi) * C_ + icg * 32 + xKK[i]);
            const unsigned short* srcx = g_xs + plane * PSTR + GUARD + n0 + dh56 + xJ[i] * 8;
            uint32_t dstx = sb + 2u * (SW_STG + xKK[i] * SX_ROW + xJ[i] * 8);
            CP16(dstx, srcx);
        }
    };

    load_chunk(0, 0); CP_COMMIT();
    load_chunk(1, 1); CP_COMMIT();

    int stage = 0;
    for (int c = 0; c < NCHUNK; c++) {
        if (c < NCHUNK - 1) { CP_WAIT(1); } else { CP_WAIT(0); }
        __syncthreads();
        if (c + 2 < NCHUNK) {
            int s2 = stage + 2; if (s2 >= NSTG) s2 -= NSTG;
            load_chunk(c + 2, s2);
            CP_COMMIT();
        }

        const uint32_t sb = sbase + (uint32_t)stage * (STG_ELEMS * 2);
        #pragma unroll
        for (int ks = 0; ks < 2; ks++) {
            uint32_t A[4][4], Bh[2][4];
            #pragma unroll
            for (int mt = 0; mt < 4; mt++) {
                uint32_t a = sb + 2u * ((aRow + mt * 16) * SW_ROW + ks * 16 + aCol);
                ldsm4(A[mt], a);
            }
            #pragma unroll
            for (int np = 0; np < 2; np++) {
                uint32_t a = sb + 2u * (SW_STG + (ks * 16 + xRow) * SX_ROW + xCol + np * 16);
                ldsm4t(Bh[np], a);
            }
            #pragma unroll
            for (int mt = 0; mt < 4; mt++)
                #pragma unroll
                for (int nt = 0; nt < 4; nt++)
                    mma_f16(acc[mt][nt], A[mt], &Bh[nt >> 1][(nt & 1) * 2]);
        }
        stage = stage + 1; if (stage >= NSTG) stage -= NSTG;
    }

    #pragma unroll
    for (int mt = 0; mt < 4; mt++) {
        #pragma unroll
        for (int nt = 0; nt < 4; nt++) {
            int o = o0 + wo + mt * 16 + gid;
            int pix = n0 + wp + nt * 8 + tid4 * 2;
            if (pix < NPIX) {
                size_t base = ((size_t)(bb * O_ + o)) * NPIX + pix;
                *(float2*)&out[base] = make_float2(acc[mt][nt][0], acc[mt][nt][1]);
                *(float2*)&out[base + (size_t)8 * NPIX] = make_float2(acc[mt][nt][2], acc[mt][nt][3]);
            }
        }
    }
}

extern "C" void kernel_launch(void* const* d_in, const int* in_sizes, int n_in,
                              void* d_out, int out_size) {
    const float* x    = (const float*)d_in[0];
    const float* kern = (const float*)d_in[1];
    const float* w1   = (const float*)d_in[2];
    const float* b1   = (const float*)d_in[3];
    const float* w2   = (const float*)d_in[4];
    const float* b2   = (const float*)d_in[5];
    float* out = (float*)d_out;

    cudaFuncSetAttribute(conv_kernel, cudaFuncAttributeMaxDynamicSharedMemorySize, SMEM_BYTES);

    split_pool_kernel<<<dim3(C_, B_), 256>>>(x);
    mlp_kernel<<<1, 256>>>(w1, b1, w2, b2);
    mix_kernel<<<NKEL / 256, 256>>>(kern);
    conv_kernel<<<dim3(GRIDX, 2, B_), 256, SMEM_BYTES>>>(out);
}

// round 8
// speedup vs baseline: 11.3002x; 1.0149x over previous
#include <cuda_runtime.h>
#include <cuda_bf16.h>
#include <cuda_fp16.h>
#include <cstdint>

// ---------------- dims ----------------
#define B_    16
#define C_    256
#define O_    256
#define HW_   56
#define NPIX  3136
#define NK    8
#define HID   64
#define KTOT  2304
#define NKEL  589824
#define PSTR  3264          // NPIX + 128 (64 guard each side)
#define GUARD 64

#define KC     64
#define NCHUNK 36           // 4 ic-groups * 9 taps
#define GRIDX  25           // ceil(3136/128) pix tiles
#define NSTG   3

// smem element offsets (fp16 units)
#define SW_ROW   72         // 64 k + 8 pad
#define SX_ROW   136        // 128 pix + 8 pad
#define SW_STG   (128 * SW_ROW)               // 9216
#define SX_STG   (64 * SX_ROW)                // 8704
#define STG_ELEMS (SW_STG + SX_STG)           // 17920
#define SMEM_BYTES (NSTG * STG_ELEMS * 2)     // 107520
#define MIX_SMEM  (8 * KTOT * 4 + 512)        // 74240

__device__ float g_pooled[B_ * C_];
__device__ float g_alphas[B_ * NK];
__device__ __align__(16) unsigned short g_wmix[(size_t)B_ * O_ * KTOT];
#define NPLANES ((size_t)B_ * 3 * C_)
__device__ __align__(16) unsigned short g_xs[NPLANES * PSTR + 64];

// ---------------- asm helpers ----------------
__device__ __forceinline__ uint32_t smem_u32(const void* p) {
    uint32_t a;
    asm("{ .reg .u64 t; cvta.to.shared.u64 t, %1; cvt.u32.u64 %0, t; }" : "=r"(a) : "l"(p));
    return a;
}
#define CP16(dst, src) asm volatile("cp.async.cg.shared.global [%0], [%1], 16;" :: "r"(dst), "l"(src))
#define CP_COMMIT()    asm volatile("cp.async.commit_group;" ::: "memory")
#define CP_WAIT(n)     asm volatile("cp.async.wait_group %0;" :: "n"(n) : "memory")

__device__ __forceinline__ void ldsm4(uint32_t* r, uint32_t a) {
    asm volatile("ldmatrix.sync.aligned.m8n8.x4.shared.b16 {%0,%1,%2,%3}, [%4];"
                 : "=r"(r[0]), "=r"(r[1]), "=r"(r[2]), "=r"(r[3]) : "r"(a));
}
__device__ __forceinline__ void ldsm4t(uint32_t* r, uint32_t a) {
    asm volatile("ldmatrix.sync.aligned.m8n8.x4.trans.shared.b16 {%0,%1,%2,%3}, [%4];"
                 : "=r"(r[0]), "=r"(r[1]), "=r"(r[2]), "=r"(r[3]) : "r"(a));
}
__device__ __forceinline__ void mma_f16(float* d, const uint32_t* a, const uint32_t* b) {
    asm volatile("mma.sync.aligned.m16n8k16.row.col.f32.f16.f16.f32 "
                 "{%0,%1,%2,%3}, {%4,%5,%6,%7}, {%8,%9}, {%0,%1,%2,%3};"
                 : "+f"(d[0]), "+f"(d[1]), "+f"(d[2]), "+f"(d[3])
                 : "r"(a[0]), "r"(a[1]), "r"(a[2]), "r"(a[3]), "r"(b[0]), "r"(b[1]));
}
__device__ __forceinline__ uint32_t h2u(float a, float b) {
    __half2 h = __floats2half2_rn(a, b);
    return *(uint32_t*)&h;
}

// ---------------- Kernel 1: x -> fp16 planes (+pool fused), vectorized ----------
__global__ void split_pool_kernel(const float* __restrict__ x) {
    const int ic = blockIdx.x, b = blockIdx.y;
    __shared__ float sp[NPIX];
    __shared__ float red[8];
    const float4* xp = (const float4*)(x + ((size_t)(b * C_ + ic)) * NPIX);
    float s = 0.f;
    for (int i = threadIdx.x; i < NPIX / 4; i += 256) {
        float4 v = xp[i];
        *(float4*)&sp[i * 4] = v;
        s += (v.x + v.y) + (v.z + v.w);
    }
    #pragma unroll
    for (int o = 16; o > 0; o >>= 1) s += __shfl_xor_sync(0xffffffffu, s, o);
    if ((threadIdx.x & 31) == 0) red[threadIdx.x >> 5] = s;
    __syncthreads();
    if (threadIdx.x < 8) {
        s = red[threadIdx.x];
        #pragma unroll
        for (int o = 4; o > 0; o >>= 1) s += __shfl_xor_sync(0xffu, s, o);
        if (threadIdx.x == 0) g_pooled[b * C_ + ic] = s * (1.0f / NPIX);
    }

    // vectorized plane stores: 8-pixel groups, groups never cross rows (8 | 56)
    for (int g = threadIdx.x; g < NPIX / 8; g += 256) {
        int p0 = g * 8;
        int w0 = p0 % HW_;
        float L  = (w0 > 0)        ? sp[p0 - 1] : 0.f;
        float Rv = (w0 + 8 < HW_)  ? sp[p0 + 8] : 0.f;
        float c0[8];
        #pragma unroll
        for (int j = 0; j < 8; j++) c0[j] = sp[p0 + j];

        uint4 v1 = make_uint4(h2u(c0[0], c0[1]), h2u(c0[2], c0[3]),
                              h2u(c0[4], c0[5]), h2u(c0[6], c0[7]));
        uint4 v0 = make_uint4(h2u(L, c0[0]), h2u(c0[1], c0[2]),
                              h2u(c0[3], c0[4]), h2u(c0[5], c0[6]));
        uint4 v2 = make_uint4(h2u(c0[1], c0[2]), h2u(c0[3], c0[4]),
                              h2u(c0[5], c0[6]), h2u(c0[7], Rv));

        *(uint4*)&g_xs[(size_t)((b * 3 + 0) * C_ + ic) * PSTR + GUARD + p0] = v0;
        *(uint4*)&g_xs[(size_t)((b * 3 + 1) * C_ + ic) * PSTR + GUARD + p0] = v1;
        *(uint4*)&g_xs[(size_t)((b * 3 + 2) * C_ + ic) * PSTR + GUARD + p0] = v2;
    }
    // guards: 3 planes x 128 elems = 384 -> 48 uint4
    if (threadIdx.x < 48) {
        int t = threadIdx.x;
        int dwi = t / 16, q = t % 16;      // q<8 front, else back
        int pos = (q < 8) ? q * 8 : (PSTR - 128 + (q - 8) * 8 + 64);
        *(uint4*)&g_xs[(size_t)((b * 3 + dwi) * C_ + ic) * PSTR + pos] = make_uint4(0, 0, 0, 0);
    }
    if (b == 0 && ic == 0 && threadIdx.x < 8)
        *(uint4*)&g_xs[NPLANES * PSTR + threadIdx.x * 8] = make_uint4(0, 0, 0, 0);
}

// ---------------- Kernel 2: MLP + softmax ----------------
__global__ void mlp_kernel(const float* __restrict__ w1, const float* __restrict__ b1,
                           const float* __restrict__ w2, const float* __restrict__ b2) {
    __shared__ float sp[B_ * C_];
    __shared__ float sh[B_ * HID];
    __shared__ float sc[B_ * NK];
    int tid = threadIdx.x;
    for (int i = tid; i < B_ * C_; i += 256) sp[i] = g_pooled[i];
    __syncthreads();
    for (int t = tid; t < B_ * HID; t += 256) {
        int b = t >> 6, j = t & 63;
        float s = b1[j];
        #pragma unroll 8
        for (int c = 0; c < C_; c++) s = fmaf(sp[b * C_ + c], w1[c * HID + j], s);
        sh[t] = fmaxf(s, 0.f);
    }
    __syncthreads();
    if (tid < B_ * NK) {
        int b = tid >> 3, k = tid & 7;
        float s = b2[k];
        #pragma unroll
        for (int j = 0; j < HID; j++) s = fmaf(sh[b * HID + j], w2[j * NK + k], s);
        sc[tid] = s;
    }
    __syncthreads();
    if (tid < B_) {
        float m = -1e30f;
        #pragma unroll
        for (int k = 0; k < NK; k++) m = fmaxf(m, sc[tid * NK + k]);
        float e[NK], sum = 0.f;
        #pragma unroll
        for (int k = 0; k < NK; k++) { e[k] = __expf(sc[tid * NK + k] - m); sum += e[k]; }
        float inv = 1.0f / sum;
        #pragma unroll
        for (int k = 0; k < NK; k++) g_alphas[tid * NK + k] = e[k] * inv;
    }
}

// ---------------- Kernel 3: weight mixing, smem-staged, coalesced ----------------
// One block per output channel o. Reads 8 banks' contiguous rows, permutes in smem.
extern __shared__ float mixsm[];
__global__ void mix_kernel(const float* __restrict__ kern) {
    float* sv = mixsm;                    // [8][KTOT]
    float* sal = mixsm + 8 * KTOT;        // [128]
    const int o = blockIdx.x, tid = threadIdx.x;
    if (tid < B_ * NK) sal[tid] = g_alphas[tid];
    #pragma unroll
    for (int k = 0; k < 8; k++)
        for (int i = tid; i < KTOT; i += 256)
            sv[k * KTOT + i] = kern[(size_t)k * NKEL + (size_t)o * KTOT + i];
    __syncthreads();

    for (int kp0 = tid * 2; kp0 < KTOT; kp0 += 512) {
        int i0 = ((kp0 & 255) * 9) + (kp0 >> 8);
        int i1 = (((kp0 + 1) & 255) * 9) + ((kp0 + 1) >> 8);
        float v0[8], v1[8];
        #pragma unroll
        for (int k = 0; k < 8; k++) { v0[k] = sv[k * KTOT + i0]; v1[k] = sv[k * KTOT + i1]; }
        #pragma unroll
        for (int b = 0; b < B_; b++) {
            float s0 = 0.f, s1 = 0.f;
            #pragma unroll
            for (int k = 0; k < 8; k++) {
                float a = sal[b * NK + k];
                s0 = fmaf(a, v0[k], s0);
                s1 = fmaf(a, v1[k], s1);
            }
            ((uint32_t*)g_wmix)[(((size_t)(b * O_ + o)) * KTOT + kp0) >> 1] = h2u(s0, s1);
        }
    }
}

// ---------------- Kernel 4: implicit-GEMM conv via mma.sync (fp16, KC=64) --------
extern __shared__ __align__(16) unsigned short dynsm[];

__global__ void __launch_bounds__(256, 2)
conv_kernel(float* __restrict__ out) {
    const int tid = threadIdx.x;
    const int n0 = blockIdx.x * 128;
    const int o0 = blockIdx.y * 128;
    const int bb = blockIdx.z;

    const int warp = tid >> 5, L = tid & 31;
    const int wo = (warp >> 2) << 6;
    const int wp = (warp & 3) << 5;
    const int gid = L >> 2, tid4 = L & 3;

    const uint32_t sbase = smem_u32(dynsm);
    const int aRow = wo + (L & 15);
    const int aCol = (L >> 4) << 3;
    const int xRow = L & 15;
    const int xCol = wp + ((L >> 4) << 3);

    int wRow[4], wJ[4], xKK[4], xJ[4];
    #pragma unroll
    for (int i = 0; i < 4; i++) {
        int e = tid + i * 256;            // 0..1023
        wRow[i] = e >> 3; wJ[i] = e & 7;
        xKK[i] = e >> 4; xJ[i] = e & 15;
    }

    float acc[4][4][4];
    #pragma unroll
    for (int mt = 0; mt < 4; mt++)
        #pragma unroll
        for (int nt = 0; nt < 4; nt++)
            #pragma unroll
            for (int r = 0; r < 4; r++) acc[mt][nt][r] = 0.f;

    auto load_chunk = [&](int c, int stg) {
        int icg = c / 9;
        int tap = c - icg * 9;
        int dwi = tap % 3;
        int dh56 = (tap / 3 - 1) * HW_;
        uint32_t sb = sbase + (uint32_t)stg * (STG_ELEMS * 2);
        #pragma unroll
        for (int i = 0; i < 4; i++) {
            const unsigned short* srcw = g_wmix
                + ((size_t)(bb * O_ + o0 + wRow[i])) * KTOT
                + tap * 256 + icg * 64 + wJ[i] * 8;
            CP16(sb + 2u * (wRow[i] * SW_ROW + wJ[i] * 8), srcw);
            size_t plane = (size_t)((bb * 3 + dwi) * C_ + icg * 64 + xKK[i]);
            const unsigned short* srcx = g_xs + plane * PSTR + GUARD + n0 + dh56 + xJ[i] * 8;
            CP16(sb + 2u * (SW_STG + xKK[i] * SX_ROW + xJ[i] * 8), srcx);
        }
    };

    load_chunk(0, 0); CP_COMMIT();
    load_chunk(1, 1); CP_COMMIT();

    int stage = 0;
    for (int c = 0; c < NCHUNK; c++) {
        if (c < NCHUNK - 1) { CP_WAIT(1); } else { CP_WAIT(0); }
        __syncthreads();
        if (c + 2 < NCHUNK) {
            int s2 = stage + 2; if (s2 >= NSTG) s2 -= NSTG;
            load_chunk(c + 2, s2);
            CP_COMMIT();
        }

        const uint32_t sb = sbase + (uint32_t)stage * (STG_ELEMS * 2);
        #pragma unroll
        for (int ks = 0; ks < 4; ks++) {
            uint32_t A[4][4], Bh[2][4];
            #pragma unroll
            for (int mt = 0; mt < 4; mt++) {
                uint32_t a = sb + 2u * ((aRow + mt * 16) * SW_ROW + ks * 16 + aCol);
                ldsm4(A[mt], a);
            }
            #pragma unroll
            for (int np = 0; np < 2; np++) {
                uint32_t a = sb + 2u * (SW_STG + (ks * 16 + xRow) * SX_ROW + xCol + np * 16);
                ldsm4t(Bh[np], a);
            }
            #pragma unroll
            for (int mt = 0; mt < 4; mt++)
                #pragma unroll
                for (int nt = 0; nt < 4; nt++)
                    mma_f16(acc[mt][nt], A[mt], &Bh[nt >> 1][(nt & 1) * 2]);
        }
        stage = stage + 1; if (stage >= NSTG) stage -= NSTG;
    }

    #pragma unroll
    for (int mt = 0; mt < 4; mt++) {
        #pragma unroll
        for (int nt = 0; nt < 4; nt++) {
            int o = o0 + wo + mt * 16 + gid;
            int pix = n0 + wp + nt * 8 + tid4 * 2;
            if (pix < NPIX) {
                size_t base = ((size_t)(bb * O_ + o)) * NPIX + pix;
                *(float2*)&out[base] = make_float2(acc[mt][nt][0], acc[mt][nt][1]);
                *(float2*)&out[base + (size_t)8 * NPIX] = make_float2(acc[mt][nt][2], acc[mt][nt][3]);
            }
        }
    }
}

extern "C" void kernel_launch(void* const* d_in, const int* in_sizes, int n_in,
                              void* d_out, int out_size) {
    const float* x    = (const float*)d_in[0];
    const float* kern = (const float*)d_in[1];
    const float* w1   = (const float*)d_in[2];
    const float* b1   = (const float*)d_in[3];
    const float* w2   = (const float*)d_in[4];
    const float* b2   = (const float*)d_in[5];
    float* out = (float*)d_out;

    cudaFuncSetAttribute(conv_kernel, cudaFuncAttributeMaxDynamicSharedMemorySize, SMEM_BYTES);
    cudaFuncSetAttribute(mix_kernel, cudaFuncAttributeMaxDynamicSharedMemorySize, MIX_SMEM);

    split_pool_kernel<<<dim3(C_, B_), 256>>>(x);
    mlp_kernel<<<1, 256>>>(w1, b1, w2, b2);
    mix_kernel<<<O_, 256, MIX_SMEM>>>(kern);
    conv_kernel<<<dim3(GRIDX, 2, B_), 256, SMEM_BYTES>>>(out);
}